// round 5
// baseline (speedup 1.0000x reference)
#include <cuda_runtime.h>
#include <math.h>

#define MAXN 25600
#define IDIM 1068
#define HID  768
#define G4   3072
#define NDOCS 128

// ---------------- scratch (static device memory; no allocs allowed) ----------
__device__ float d_xpad[(MAXN + 6) * IDIM];            // pos-encoded input, 3 zero rows each side
__device__ float d_cwt[15 * IDIM * 256];               // conv weights transposed, per-tap planes
__device__ float d_wtih[HID * G4];                     // W_ih^T   [768,3072]
__device__ float d_wthh[HID * G4];                     // W_hh^T
__device__ float d_wtihr[HID * G4];
__device__ float d_wthhr[HID * G4];
__device__ float d_bsum[G4], d_bsumr[G4];
__device__ float d_xfeat[MAXN * HID];                  // leaky(conv) features
__device__ float d_xpool[MAXN * HID];                  // maxpooled features
__device__ float d_G[(size_t)MAXN * G4];               // gate buffer (reused 3x)
__device__ float d_hbuf[(MAXN + 18) * HID];            // h with 9 zero rows each side
__device__ float d_cbuf[(MAXN + 18) * HID];
__device__ int   d_pos[MAXN];
__device__ int   d_off[NDOCS + 1];
__device__ unsigned d_bar;

// Buffer IDs (device-side pointer resolution; NO cudaGetSymbolAddress on host)
#define B_XPAD  0
#define B_CWT   1
#define B_WTIH  2
#define B_WTHH  3
#define B_WTIHR 4
#define B_WTHHR 5
#define B_XFEAT 6
#define B_XPOOL 7
#define B_G     8
#define B_HBUF  9
#define B_BSUM  10
#define B_BSUMR 11

__device__ __forceinline__ float* buf_of(int id)
{
    switch (id) {
        case B_XPAD:  return d_xpad;
        case B_CWT:   return d_cwt;
        case B_WTIH:  return d_wtih;
        case B_WTHH:  return d_wthh;
        case B_WTIHR: return d_wtihr;
        case B_WTHHR: return d_wthhr;
        case B_XFEAT: return d_xfeat;
        case B_XPOOL: return d_xpool;
        case B_G:     return d_G;
        case B_HBUF:  return d_hbuf;
        case B_BSUM:  return d_bsum;
        case B_BSUMR: return d_bsumr;
        default:      return 0;
    }
}

__device__ __forceinline__ float sigm(float x) { return 1.f / (1.f + expf(-x)); }

// ---------------- small setup kernels ---------------------------------------
__global__ void k_init(const int* __restrict__ lens)
{
    if (blockIdx.x == 0 && threadIdx.x == 0) {
        int s = 0; d_off[0] = 0;
        for (int i = 0; i < NDOCS; i++) { s += lens[i]; d_off[i + 1] = s; }
        d_bar = 0u;
    }
}

__global__ void k_pos(int N)
{
    int n = blockIdx.x * blockDim.x + threadIdx.x;
    if (n >= N) return;
    int lo = 0, hi = NDOCS;
    while (hi - lo > 1) { int mid = (lo + hi) >> 1; if (d_off[mid] <= n) lo = mid; else hi = mid; }
    d_pos[n] = n - d_off[lo];
}

__global__ void k_xpad(const float* __restrict__ x, int N)
{
    int idx = blockIdx.x * blockDim.x + threadIdx.x;
    int total = (N + 6) * IDIM;
    if (idx >= total) return;
    int r = idx / IDIM, dd = idx % IDIM;
    if (r < 3 || r >= N + 3) { d_xpad[idx] = 0.f; return; }
    int n = r - 3;
    int p = d_pos[n];
    int i = dd >> 1;
    float denom = powf(10000.f, (2.f * (float)i) / 1068.f);
    float ang = (float)p / denom;
    float pe = (dd & 1) ? cosf(ang) : sinf(ang);
    d_xpad[idx] = x[(size_t)n * IDIM + dd] + pe;
}

// conv weight transpose: w[oc,in,k] -> planes [j][in][oc] at d_cwt + planeBase
__global__ void k_tconv(const float* __restrict__ w, int k, size_t dstOff)
{
    int idx = blockIdx.x * blockDim.x + threadIdx.x;
    int total = k * IDIM * 256;
    if (idx >= total) return;
    int j = idx / (IDIM * 256);
    int r = idx % (IDIM * 256);
    int d = r / 256, c = r % 256;
    d_cwt[dstOff + idx] = w[(size_t)c * IDIM * k + (size_t)d * k + j];
}

// lstm weight transpose: W[3072,768] -> Wt[768,3072]
__global__ void k_tlstm(const float* __restrict__ w, int dstId)
{
    int idx = blockIdx.x * blockDim.x + threadIdx.x;
    if (idx >= HID * G4) return;
    int f = idx / G4, g = idx % G4;
    buf_of(dstId)[idx] = w[(size_t)g * HID + f];
}

__global__ void k_bsum(const float* __restrict__ a, const float* __restrict__ b, int dstId)
{
    int i = blockIdx.x * blockDim.x + threadIdx.x;
    if (i < G4) buf_of(dstId)[i] = a[i] + b[i];
}

__global__ void k_leaky(int n)
{
    int i = blockIdx.x * blockDim.x + threadIdx.x;
    if (i >= n) return;
    float v = d_xfeat[i];
    d_xfeat[i] = (v >= 0.f) ? v : 0.01f * v;
}

__global__ void k_pool(int N)
{
    int idx = blockIdx.x * blockDim.x + threadIdx.x;
    if (idx >= N * HID) return;
    int n = idx / HID, f = idx % HID;
    int p = (f < 256) ? 1 : ((f < 512) ? 2 : 3);
    int lo = n - p; if (lo < 0) lo = 0;
    int hi = n + p; if (hi > N - 1) hi = N - 1;
    float v = -INFINITY;
    for (int m = lo; m <= hi; m++) {
        float u = d_xfeat[(size_t)m * HID + f];
        v = (u > v) ? u : v;
    }
    d_xpool[idx] = v;
}

__global__ void k_zero_hc(int N)
{
    int idx = blockIdx.x * blockDim.x + threadIdx.x;
    if (idx >= 18 * HID) return;
    int i = idx / HID, ch = idx % HID;
    int row = (i < 9) ? i : (N + i);          // rows [0,9) and [N+9,N+18)
    d_hbuf[(size_t)row * HID + ch] = 0.f;
    d_cbuf[(size_t)row * HID + ch] = 0.f;
}

// ---------------- SGEMM: C[M,N] (=|+=) A[M,K] @ B[K,N] (+ bias) -------------
__global__ void __launch_bounds__(256, 2) sgemm_k(
    int aid, size_t aoff, int lda,
    int bid, size_t boff, int ldb,
    int cid, size_t coff, int ldc,
    int M, int N, int K,
    const float* __restrict__ bias_ext, int bias_id, int accflag)
{
    const float* A = buf_of(aid) + aoff;
    const float* B = buf_of(bid) + boff;
    float*       C = buf_of(cid) + coff;
    const float* bias = (bias_id >= 0) ? buf_of(bias_id) : bias_ext;

    __shared__ __align__(16) float As[8][132];
    __shared__ __align__(16) float Bs[8][128];
    const int bm = blockIdx.y * 128, bn = blockIdx.x * 128;
    const int tid = threadIdx.x;
    const int tr = tid >> 4, tc = tid & 15;
    const int am = tid >> 3, ak = tid & 7;
    const int bn0 = tid & 127, bk0 = tid >> 7;

    float acc[8][8];
#pragma unroll
    for (int i = 0; i < 8; i++)
#pragma unroll
        for (int j = 0; j < 8; j++) acc[i][j] = 0.f;

    for (int k0 = 0; k0 < K; k0 += 8) {
#pragma unroll
        for (int i = 0; i < 4; i++) {
            int m = bm + am + 32 * i;
            int kk = k0 + ak;
            As[ak][am + 32 * i] = (m < M && kk < K) ? A[(size_t)m * lda + kk] : 0.f;
        }
#pragma unroll
        for (int i = 0; i < 4; i++) {
            int kk = k0 + bk0 + 2 * i;
            int n = bn + bn0;
            Bs[bk0 + 2 * i][bn0] = (kk < K && n < N) ? B[(size_t)kk * ldb + n] : 0.f;
        }
        __syncthreads();
#pragma unroll
        for (int kk = 0; kk < 8; kk++) {
            float4 a0 = *(const float4*)&As[kk][tr * 8];
            float4 a1 = *(const float4*)&As[kk][tr * 8 + 4];
            float4 b0 = *(const float4*)&Bs[kk][tc * 8];
            float4 b1 = *(const float4*)&Bs[kk][tc * 8 + 4];
            float av[8] = {a0.x, a0.y, a0.z, a0.w, a1.x, a1.y, a1.z, a1.w};
            float bv[8] = {b0.x, b0.y, b0.z, b0.w, b1.x, b1.y, b1.z, b1.w};
#pragma unroll
            for (int i = 0; i < 8; i++)
#pragma unroll
                for (int j = 0; j < 8; j++) acc[i][j] += av[i] * bv[j];
        }
        __syncthreads();
    }

#pragma unroll
    for (int i = 0; i < 8; i++) {
        int m = bm + tr * 8 + i;
        if (m < M) {
            float* crow = C + (size_t)m * ldc;
#pragma unroll
            for (int j = 0; j < 8; j++) {
                int n = bn + tc * 8 + j;
                if (n < N) {
                    if (accflag) crow[n] += acc[i][j];
                    else crow[n] = acc[i][j] + (bias ? bias[n] : 0.f);
                }
            }
        }
    }
}

// ---------------- persistent chunked-LSTM scan -------------------------------
// 128 blocks, 6 h-columns each (128*6=768). Per step: gates = G[row] + h_prev@W_hh^T.
// Dynamic smem: 16*768 floats = 49152 B exactly (gate staging carved from it).
#define SCAN_NB 128
#define COLS_PB 6

__global__ void __launch_bounds__(256) scan_k(const float* __restrict__ Whh,
                                              int N, int n_chunks)
{
    extern __shared__ float sh[];                  // [16*768] h chunk; reused for gate staging
    const int tid = threadIdx.x;
    const int lane = tid & 31, warp = tid >> 5;
    const int colBase = blockIdx.x * COLS_PB;
    unsigned target = 0;

    for (int t = 0; t < n_chunks; ++t) {
        // load h_prev chunk (rows (t-1)*16 .. +15) into smem
        if (t == 0) {
            for (int i = tid; i < 16 * HID; i += 256) sh[i] = 0.f;
        } else {
            const float* src = d_hbuf + (size_t)(9 + (t - 1) * 16) * HID;
            for (int i = tid; i < 16 * HID; i += 256) sh[i] = __ldcg(src + i);
        }
        __syncthreads();

        // 24 (gate,col) pairs per block, 3 per warp; accumulate 16 rows each
        float acc[3][16];
#pragma unroll
        for (int p = 0; p < 3; p++)
#pragma unroll
            for (int r = 0; r < 16; r++) acc[p][r] = 0.f;

        const float* wrow[3];
#pragma unroll
        for (int p = 0; p < 3; p++) {
            int pp = warp * 3 + p;
            int gate = pp / COLS_PB, cl = pp % COLS_PB;
            wrow[p] = Whh + (size_t)(gate * HID + colBase + cl) * HID;
        }
#pragma unroll 4
        for (int it = 0; it < 24; ++it) {
            int f = lane + 32 * it;
            float hreg[16];
#pragma unroll
            for (int r = 0; r < 16; r++) hreg[r] = sh[r * HID + f];
#pragma unroll
            for (int p = 0; p < 3; p++) {
                float w = __ldg(wrow[p] + f);
#pragma unroll
                for (int r = 0; r < 16; r++) acc[p][r] += w * hreg[r];
            }
        }
        __syncthreads();   // all sh reads done; safe to reuse sh[0..383] as gate staging

#pragma unroll
        for (int p = 0; p < 3; p++) {
            int pp = warp * 3 + p;
            int gate = pp / COLS_PB, cl = pp % COLS_PB;
#pragma unroll
            for (int r = 0; r < 16; r++) {
                float v = acc[p][r];
                v += __shfl_down_sync(0xffffffffu, v, 16);
                v += __shfl_down_sync(0xffffffffu, v, 8);
                v += __shfl_down_sync(0xffffffffu, v, 4);
                v += __shfl_down_sync(0xffffffffu, v, 2);
                v += __shfl_down_sync(0xffffffffu, v, 1);
                if (lane == 0) sh[(cl * 4 + gate) * 16 + r] = v;
            }
        }
        __syncthreads();

        if (tid < 16 * COLS_PB) {
            int r = tid & 15, cl = tid >> 4;
            int n = t * 16 + r;
            if (n < N) {
                int col = colBase + cl;
                const float* g = d_G + (size_t)n * G4;
                float gi = g[col]        + sh[(cl * 4 + 0) * 16 + r];
                float gf = g[col + 768]  + sh[(cl * 4 + 1) * 16 + r];
                float gg = g[col + 1536] + sh[(cl * 4 + 2) * 16 + r];
                float go = g[col + 2304] + sh[(cl * 4 + 3) * 16 + r];
                float cp = (t == 0) ? 0.f : d_cbuf[(size_t)(9 + n - 16) * HID + col];
                float c2 = sigm(gf) * cp + sigm(gi) * tanhf(gg);
                d_hbuf[(size_t)(9 + n) * HID + col] = sigm(go) * tanhf(c2);
                d_cbuf[(size_t)(9 + n) * HID + col] = c2;
            }
        }
        // grid barrier (release: fence + atomic; acquire: spin + fence)
        __threadfence();
        __syncthreads();
        target += gridDim.x;
        if (tid == 0) {
            atomicAdd(&d_bar, 1u);
            while (*((volatile unsigned*)&d_bar) < target) { __nanosleep(20); }
        }
        __syncthreads();
        __threadfence();
    }
}

// ---------------- final LSTM cell epilogue ------------------------------------
__global__ void k_final(float* __restrict__ out, int N, int rev)
{
    int idx = blockIdx.x * blockDim.x + threadIdx.x;
    if (idx >= N * HID) return;
    int n = idx / HID, ch = idx % HID;
    const float* g = d_G + (size_t)n * G4;
    float gi = sigm(g[ch]);
    float gf = sigm(g[ch + 768]);
    float gg = tanhf(g[ch + 1536]);
    float go = sigm(g[ch + 2304]);
    float cp = d_cbuf[(size_t)(n + (rev ? 18 : 0)) * HID + ch];
    float c2 = gf * cp + gi * gg;
    out[(size_t)n * 1536 + (rev ? 768 : 0) + ch] = go * tanhf(c2);
}

// ---------------- host side ---------------------------------------------------
static inline int ceil_div(int a, int b) { return (a + b - 1) / b; }

static void gemm(int aid, size_t aoff, int lda, int bid, size_t boff, int ldb,
                 int cid, size_t coff, int ldc, int M, int N, int K,
                 const float* bias_ext, int bias_id, int acc)
{
    dim3 g(ceil_div(N, 128), ceil_div(M, 128));
    sgemm_k<<<g, 256>>>(aid, aoff, lda, bid, boff, ldb, cid, coff, ldc,
                        M, N, K, bias_ext, bias_id, acc);
}

extern "C" void kernel_launch(void* const* d_in, const int* in_sizes, int n_in,
                              void* d_out, int out_size)
{
    const float* x      = (const float*)d_in[0];
    const int*   lens   = (const int*)d_in[1];
    const float* cw[3]  = {(const float*)d_in[2], (const float*)d_in[4], (const float*)d_in[6]};
    const float* cb[3]  = {(const float*)d_in[3], (const float*)d_in[5], (const float*)d_in[7]};
    const float* W_ih   = (const float*)d_in[8];
    const float* W_hh   = (const float*)d_in[9];
    const float* b_ih   = (const float*)d_in[10];
    const float* b_hh   = (const float*)d_in[11];
    const float* W_ihr  = (const float*)d_in[12];
    const float* W_hhr  = (const float*)d_in[13];
    const float* b_ihr  = (const float*)d_in[14];
    const float* b_hhr  = (const float*)d_in[15];
    float* out = (float*)d_out;

    const int N = out_size / 1536;
    const int n_chunks = (N + 15) / 16;

    // setup
    k_init<<<1, 32>>>(lens);
    k_pos<<<ceil_div(N, 256), 256>>>(N);
    k_xpad<<<ceil_div((N + 6) * IDIM, 256), 256>>>(x, N);

    const int ks[3] = {3, 5, 7};
    const int planeBase[3] = {0, 3, 8};
    for (int c = 0; c < 3; c++)
        k_tconv<<<ceil_div(ks[c] * IDIM * 256, 256), 256>>>(cw[c], ks[c],
                                                            (size_t)planeBase[c] * IDIM * 256);
    k_tlstm<<<ceil_div(HID * G4, 256), 256>>>(W_ih,  B_WTIH);
    k_tlstm<<<ceil_div(HID * G4, 256), 256>>>(W_hh,  B_WTHH);
    k_tlstm<<<ceil_div(HID * G4, 256), 256>>>(W_ihr, B_WTIHR);
    k_tlstm<<<ceil_div(HID * G4, 256), 256>>>(W_hhr, B_WTHHR);
    k_bsum<<<ceil_div(G4, 256), 256>>>(b_ih,  b_hh,  B_BSUM);
    k_bsum<<<ceil_div(G4, 256), 256>>>(b_ihr, b_hhr, B_BSUMR);

    // conv as shifted GEMMs, accumulate taps into xfeat
    for (int c = 0; c < 3; c++) {
        int k = ks[c], p = k / 2, chOff = 256 * c;
        for (int j = 0; j < k; j++) {
            gemm(B_XPAD, (size_t)(3 + j - p) * IDIM, IDIM,
                 B_CWT, (size_t)(planeBase[c] + j) * IDIM * 256, 256,
                 B_XFEAT, (size_t)chOff, HID,
                 N, 256, IDIM,
                 (j == 0) ? cb[c] : (const float*)0, -1, (j == 0) ? 0 : 1);
        }
    }
    k_leaky<<<ceil_div(N * HID, 256), 256>>>(N * HID);
    k_pool<<<ceil_div(N * HID, 256), 256>>>(N);

    // scan gates x-part: G = xpool @ Wih^T + (b_ih + b_hh)
    gemm(B_XPOOL, 0, HID, B_WTIH, 0, G4, B_G, 0, G4, N, G4, HID, 0, B_BSUM, 0);
    k_zero_hc<<<ceil_div(18 * HID, 256), 256>>>(N);
    scan_k<<<SCAN_NB, 256, 16 * HID * sizeof(float)>>>(W_hh, N, n_chunks);

    // forward final cell: gates = xfeat@Wih^T + bsum + h_prev@Whh^T
    gemm(B_XFEAT, 0, HID, B_WTIH, 0, G4, B_G, 0, G4, N, G4, HID, 0, B_BSUM, 0);
    gemm(B_HBUF, 0, HID, B_WTHH, 0, G4, B_G, 0, G4, N, G4, HID, 0, -1, 1);
    k_final<<<ceil_div(N * HID, 256), 256>>>(out, N, 0);

    // reverse final cell: gates = xfeat@Wihr^T + bsumr + h_next@Whhr^T
    gemm(B_XFEAT, 0, HID, B_WTIHR, 0, G4, B_G, 0, G4, N, G4, HID, 0, B_BSUMR, 0);
    gemm(B_HBUF, (size_t)18 * HID, HID, B_WTHHR, 0, G4, B_G, 0, G4, N, G4, HID, 0, -1, 1);
    k_final<<<ceil_div(N * HID, 256), 256>>>(out, N, 1);
}

// round 7
// speedup vs baseline: 1.0578x; 1.0578x over previous
#include <cuda_runtime.h>
#include <math.h>

#define MAXN 25600
#define IDIM 1068
#define HID  768
#define G4   3072
#define NDOCS 128

// ---------------- scratch (static device memory; no allocs allowed) ----------
__device__ float d_xpad[(MAXN + 6) * IDIM];            // pos-encoded input, 3 zero rows each side
__device__ float d_cwt[15 * IDIM * 256];               // conv weights transposed, per-tap planes
__device__ float d_wtih[HID * G4];                     // W_ih^T   [768,3072]
__device__ float d_wthh[HID * G4];                     // W_hh^T
__device__ float d_wtihr[HID * G4];
__device__ float d_wthhr[HID * G4];
__device__ float d_bsum[G4], d_bsumr[G4];
__device__ float d_xfeat[MAXN * HID];                  // leaky(conv) features
__device__ float d_xpool[MAXN * HID];                  // maxpooled features
__device__ float d_G[(size_t)MAXN * G4];               // gate buffer (reused 3x)
__device__ float d_hbuf[(MAXN + 18) * HID];            // h with 9 zero rows each side
__device__ float d_cbuf[(MAXN + 18) * HID];
__device__ int   d_pos[MAXN];
__device__ int   d_off[NDOCS + 1];
__device__ unsigned d_bar;

// Buffer IDs (device-side pointer resolution; NO cudaGetSymbolAddress on host)
#define B_XPAD  0
#define B_CWT   1
#define B_WTIH  2
#define B_WTHH  3
#define B_WTIHR 4
#define B_WTHHR 5
#define B_XFEAT 6
#define B_XPOOL 7
#define B_G     8
#define B_HBUF  9
#define B_BSUM  10
#define B_BSUMR 11

__device__ __forceinline__ float* buf_of(int id)
{
    switch (id) {
        case B_XPAD:  return d_xpad;
        case B_CWT:   return d_cwt;
        case B_WTIH:  return d_wtih;
        case B_WTHH:  return d_wthh;
        case B_WTIHR: return d_wtihr;
        case B_WTHHR: return d_wthhr;
        case B_XFEAT: return d_xfeat;
        case B_XPOOL: return d_xpool;
        case B_G:     return d_G;
        case B_HBUF:  return d_hbuf;
        case B_BSUM:  return d_bsum;
        case B_BSUMR: return d_bsumr;
        default:      return 0;
    }
}

__device__ __forceinline__ float sigm(float x) { return 1.f / (1.f + expf(-x)); }

// packed fp32x2 helpers (FFMA2 path — ptxas never emits this from C++)
__device__ __forceinline__ unsigned long long bcast2(float x)
{
    unsigned long long r;
    asm("mov.b64 %0, {%1, %1};" : "=l"(r) : "r"(__float_as_uint(x)));
    return r;
}
__device__ __forceinline__ void ffma2(unsigned long long& d,
                                      unsigned long long a, unsigned long long b)
{
    asm("fma.rn.f32x2 %0, %1, %2, %0;" : "+l"(d) : "l"(a), "l"(b));
}
union F4U2 { float4 f; unsigned long long u[2]; };

// ---------------- small setup kernels ---------------------------------------
__global__ void k_init(const int* __restrict__ lens)
{
    if (blockIdx.x == 0 && threadIdx.x == 0) {
        int s = 0; d_off[0] = 0;
        for (int i = 0; i < NDOCS; i++) { s += lens[i]; d_off[i + 1] = s; }
        d_bar = 0u;
    }
}

__global__ void k_pos(int N)
{
    int n = blockIdx.x * blockDim.x + threadIdx.x;
    if (n >= N) return;
    int lo = 0, hi = NDOCS;
    while (hi - lo > 1) { int mid = (lo + hi) >> 1; if (d_off[mid] <= n) lo = mid; else hi = mid; }
    d_pos[n] = n - d_off[lo];
}

__global__ void k_xpad(const float* __restrict__ x, int N)
{
    int idx = blockIdx.x * blockDim.x + threadIdx.x;
    int total = (N + 6) * IDIM;
    if (idx >= total) return;
    int r = idx / IDIM, dd = idx % IDIM;
    if (r < 3 || r >= N + 3) { d_xpad[idx] = 0.f; return; }
    int n = r - 3;
    int p = d_pos[n];
    int i = dd >> 1;
    float denom = powf(10000.f, (2.f * (float)i) / 1068.f);
    float ang = (float)p / denom;
    float pe = (dd & 1) ? cosf(ang) : sinf(ang);
    d_xpad[idx] = x[(size_t)n * IDIM + dd] + pe;
}

// conv weight transpose: w[oc,in,k] -> planes [j][in][oc] at d_cwt + planeBase
__global__ void k_tconv(const float* __restrict__ w, int k, size_t dstOff)
{
    int idx = blockIdx.x * blockDim.x + threadIdx.x;
    int total = k * IDIM * 256;
    if (idx >= total) return;
    int j = idx / (IDIM * 256);
    int r = idx % (IDIM * 256);
    int d = r / 256, c = r % 256;
    d_cwt[dstOff + idx] = w[(size_t)c * IDIM * k + (size_t)d * k + j];
}

// lstm weight transpose: W[3072,768] -> Wt[768,3072]
__global__ void k_tlstm(const float* __restrict__ w, int dstId)
{
    int idx = blockIdx.x * blockDim.x + threadIdx.x;
    if (idx >= HID * G4) return;
    int f = idx / G4, g = idx % G4;
    buf_of(dstId)[idx] = w[(size_t)g * HID + f];
}

__global__ void k_bsum(const float* __restrict__ a, const float* __restrict__ b, int dstId)
{
    int i = blockIdx.x * blockDim.x + threadIdx.x;
    if (i < G4) buf_of(dstId)[i] = a[i] + b[i];
}

__global__ void k_pool(int N)
{
    int idx = blockIdx.x * blockDim.x + threadIdx.x;
    if (idx >= N * HID) return;
    int n = idx / HID, f = idx % HID;
    int p = (f < 256) ? 1 : ((f < 512) ? 2 : 3);
    int lo = n - p; if (lo < 0) lo = 0;
    int hi = n + p; if (hi > N - 1) hi = N - 1;
    float v = -INFINITY;
    for (int m = lo; m <= hi; m++) {
        float u = d_xfeat[(size_t)m * HID + f];
        v = (u > v) ? u : v;
    }
    d_xpool[idx] = v;
}

__global__ void k_zero_hc(int N)
{
    int idx = blockIdx.x * blockDim.x + threadIdx.x;
    if (idx >= 18 * HID) return;
    int i = idx / HID, ch = idx % HID;
    int row = (i < 9) ? i : (N + i);          // rows [0,9) and [N+9,N+18)
    d_hbuf[(size_t)row * HID + ch] = 0.f;
    d_cbuf[(size_t)row * HID + ch] = 0.f;
}

// ---------------- SGEMM (f32x2): C[M,N] (=|+=) A[M,K] @ B[K,N] ---------------
// optional bias add + optional LeakyReLU in epilogue
__global__ void __launch_bounds__(256, 2) sgemm_k(
    int aid, size_t aoff, int lda,
    int bid, size_t boff, int ldb,
    int cid, size_t coff, int ldc,
    int M, int N, int K,
    const float* __restrict__ bias_ext, int bias_id, int accflag, int leakyflag)
{
    const float* A = buf_of(aid) + aoff;
    const float* B = buf_of(bid) + boff;
    float*       C = buf_of(cid) + coff;
    const float* bias = (bias_id >= 0) ? buf_of(bias_id) : bias_ext;

    __shared__ __align__(16) float As[8][132];
    __shared__ __align__(16) float Bs[8][128];
    const int bm = blockIdx.y * 128, bn = blockIdx.x * 128;
    const int tid = threadIdx.x;
    const int tr = tid >> 4, tc = tid & 15;
    const int am = tid >> 3, ak = tid & 7;
    const int bn0 = tid & 127, bk0 = tid >> 7;

    unsigned long long acc2[8][4];
#pragma unroll
    for (int i = 0; i < 8; i++)
#pragma unroll
        for (int j = 0; j < 4; j++) acc2[i][j] = 0ull;

    for (int k0 = 0; k0 < K; k0 += 8) {
#pragma unroll
        for (int i = 0; i < 4; i++) {
            int m = bm + am + 32 * i;
            int kk = k0 + ak;
            As[ak][am + 32 * i] = (m < M && kk < K) ? A[(size_t)m * lda + kk] : 0.f;
        }
#pragma unroll
        for (int i = 0; i < 4; i++) {
            int kk = k0 + bk0 + 2 * i;
            int n = bn + bn0;
            Bs[bk0 + 2 * i][bn0] = (kk < K && n < N) ? B[(size_t)kk * ldb + n] : 0.f;
        }
        __syncthreads();
#pragma unroll
        for (int kk = 0; kk < 8; kk++) {
            float4 a0 = *(const float4*)&As[kk][tr * 8];
            float4 a1 = *(const float4*)&As[kk][tr * 8 + 4];
            F4U2 b0, b1;
            b0.f = *(const float4*)&Bs[kk][tc * 8];
            b1.f = *(const float4*)&Bs[kk][tc * 8 + 4];
            unsigned long long bb[4] = {b0.u[0], b0.u[1], b1.u[0], b1.u[1]};
            float av[8] = {a0.x, a0.y, a0.z, a0.w, a1.x, a1.y, a1.z, a1.w};
#pragma unroll
            for (int i = 0; i < 8; i++) {
                unsigned long long aa = bcast2(av[i]);
#pragma unroll
                for (int j = 0; j < 4; j++) ffma2(acc2[i][j], aa, bb[j]);
            }
        }
        __syncthreads();
    }

#pragma unroll
    for (int i = 0; i < 8; i++) {
        int m = bm + tr * 8 + i;
        if (m < M) {
            float* crow = C + (size_t)m * ldc;
#pragma unroll
            for (int j = 0; j < 4; j++) {
#pragma unroll
                for (int h = 0; h < 2; h++) {
                    int n = bn + tc * 8 + 2 * j + h;
                    if (n < N) {
                        float v = h ? __uint_as_float((unsigned)(acc2[i][j] >> 32))
                                    : __uint_as_float((unsigned)acc2[i][j]);
                        if (accflag) {
                            crow[n] += v;
                        } else {
                            v += (bias ? bias[n] : 0.f);
                            if (leakyflag) v = (v >= 0.f) ? v : 0.01f * v;
                            crow[n] = v;
                        }
                    }
                }
            }
        }
    }
}

// ---------------- persistent chunked-LSTM scan -------------------------------
// 128 blocks, 6 h-columns each (128*6=768). Per step: gates = G[row] + h_prev@W_hh^T.
// Dynamic smem: 16*768 floats = 49152 B exactly (gate staging carved from it).
#define SCAN_NB 128
#define COLS_PB 6

__global__ void __launch_bounds__(256) scan_k(const float* __restrict__ Whh,
                                              int N, int n_chunks)
{
    extern __shared__ float sh[];                  // [16*768] h chunk; reused for gate staging
    const int tid = threadIdx.x;
    const int lane = tid & 31, warp = tid >> 5;
    const int colBase = blockIdx.x * COLS_PB;
    unsigned target = 0;

    for (int t = 0; t < n_chunks; ++t) {
        // load h_prev chunk (rows (t-1)*16 .. +15) into smem
        if (t == 0) {
            for (int i = tid; i < 16 * HID; i += 256) sh[i] = 0.f;
        } else {
            const float* src = d_hbuf + (size_t)(9 + (t - 1) * 16) * HID;
            for (int i = tid; i < 16 * HID; i += 256) sh[i] = __ldcg(src + i);
        }
        __syncthreads();

        // 24 (gate,col) pairs per block, 3 per warp; accumulate 16 rows each
        float acc[3][16];
#pragma unroll
        for (int p = 0; p < 3; p++)
#pragma unroll
            for (int r = 0; r < 16; r++) acc[p][r] = 0.f;

        const float* wrow[3];
#pragma unroll
        for (int p = 0; p < 3; p++) {
            int pp = warp * 3 + p;
            int gate = pp / COLS_PB, cl = pp % COLS_PB;
            wrow[p] = Whh + (size_t)(gate * HID + colBase + cl) * HID;
        }
#pragma unroll 4
        for (int it = 0; it < 24; ++it) {
            int f = lane + 32 * it;
            float hreg[16];
#pragma unroll
            for (int r = 0; r < 16; r++) hreg[r] = sh[r * HID + f];
#pragma unroll
            for (int p = 0; p < 3; p++) {
                float w = __ldg(wrow[p] + f);
#pragma unroll
                for (int r = 0; r < 16; r++) acc[p][r] += w * hreg[r];
            }
        }
        __syncthreads();   // all sh reads done; safe to reuse sh[0..383] as gate staging

#pragma unroll
        for (int p = 0; p < 3; p++) {
            int pp = warp * 3 + p;
            int gate = pp / COLS_PB, cl = pp % COLS_PB;
#pragma unroll
            for (int r = 0; r < 16; r++) {
                float v = acc[p][r];
                v += __shfl_down_sync(0xffffffffu, v, 16);
                v += __shfl_down_sync(0xffffffffu, v, 8);
                v += __shfl_down_sync(0xffffffffu, v, 4);
                v += __shfl_down_sync(0xffffffffu, v, 2);
                v += __shfl_down_sync(0xffffffffu, v, 1);
                if (lane == 0) sh[(cl * 4 + gate) * 16 + r] = v;
            }
        }
        __syncthreads();

        if (tid < 16 * COLS_PB) {
            int r = tid & 15, cl = tid >> 4;
            int n = t * 16 + r;
            if (n < N) {
                int col = colBase + cl;
                const float* g = d_G + (size_t)n * G4;
                float gi = g[col]        + sh[(cl * 4 + 0) * 16 + r];
                float gf = g[col + 768]  + sh[(cl * 4 + 1) * 16 + r];
                float gg = g[col + 1536] + sh[(cl * 4 + 2) * 16 + r];
                float go = g[col + 2304] + sh[(cl * 4 + 3) * 16 + r];
                float cp = (t == 0) ? 0.f : d_cbuf[(size_t)(9 + n - 16) * HID + col];
                float c2 = sigm(gf) * cp + sigm(gi) * tanhf(gg);
                d_hbuf[(size_t)(9 + n) * HID + col] = sigm(go) * tanhf(c2);
                d_cbuf[(size_t)(9 + n) * HID + col] = c2;
            }
        }
        // grid barrier (release: fence + atomic; acquire: spin + fence)
        __threadfence();
        __syncthreads();
        target += gridDim.x;
        if (tid == 0) {
            atomicAdd(&d_bar, 1u);
            while (*((volatile unsigned*)&d_bar) < target) { __nanosleep(20); }
        }
        __syncthreads();
        __threadfence();
    }
}

// ---------------- final LSTM cell epilogue ------------------------------------
__global__ void k_final(float* __restrict__ out, int N, int rev)
{
    int idx = blockIdx.x * blockDim.x + threadIdx.x;
    if (idx >= N * HID) return;
    int n = idx / HID, ch = idx % HID;
    const float* g = d_G + (size_t)n * G4;
    float gi = sigm(g[ch]);
    float gf = sigm(g[ch + 768]);
    float gg = tanhf(g[ch + 1536]);
    float go = sigm(g[ch + 2304]);
    float cp = d_cbuf[(size_t)(n + (rev ? 18 : 0)) * HID + ch];
    float c2 = gf * cp + gi * gg;
    out[(size_t)n * 1536 + (rev ? 768 : 0) + ch] = go * tanhf(c2);
}

// ---------------- host side ---------------------------------------------------
static inline int ceil_div(int a, int b) { return (a + b - 1) / b; }

static void gemm(int aid, size_t aoff, int lda, int bid, size_t boff, int ldb,
                 int cid, size_t coff, int ldc, int M, int N, int K,
                 const float* bias_ext, int bias_id, int acc, int leaky = 0)
{
    dim3 g(ceil_div(N, 128), ceil_div(M, 128));
    sgemm_k<<<g, 256>>>(aid, aoff, lda, bid, boff, ldb, cid, coff, ldc,
                        M, N, K, bias_ext, bias_id, acc, leaky);
}

extern "C" void kernel_launch(void* const* d_in, const int* in_sizes, int n_in,
                              void* d_out, int out_size)
{
    const float* x      = (const float*)d_in[0];
    const int*   lens   = (const int*)d_in[1];
    const float* cw[3]  = {(const float*)d_in[2], (const float*)d_in[4], (const float*)d_in[6]};
    const float* cb[3]  = {(const float*)d_in[3], (const float*)d_in[5], (const float*)d_in[7]};
    const float* W_ih   = (const float*)d_in[8];
    const float* W_hh   = (const float*)d_in[9];
    const float* b_ih   = (const float*)d_in[10];
    const float* b_hh   = (const float*)d_in[11];
    const float* W_ihr  = (const float*)d_in[12];
    const float* W_hhr  = (const float*)d_in[13];
    const float* b_ihr  = (const float*)d_in[14];
    const float* b_hhr  = (const float*)d_in[15];
    float* out = (float*)d_out;

    const int N = out_size / 1536;
    const int n_chunks = (N + 15) / 16;

    // setup
    k_init<<<1, 32>>>(lens);
    k_pos<<<ceil_div(N, 256), 256>>>(N);
    k_xpad<<<ceil_div((N + 6) * IDIM, 256), 256>>>(x, N);

    const int ks[3] = {3, 5, 7};
    const int planeBase[3] = {0, 3, 8};
    for (int c = 0; c < 3; c++)
        k_tconv<<<ceil_div(ks[c] * IDIM * 256, 256), 256>>>(cw[c], ks[c],
                                                            (size_t)planeBase[c] * IDIM * 256);
    k_tlstm<<<ceil_div(HID * G4, 256), 256>>>(W_ih,  B_WTIH);
    k_tlstm<<<ceil_div(HID * G4, 256), 256>>>(W_hh,  B_WTHH);
    k_tlstm<<<ceil_div(HID * G4, 256), 256>>>(W_ihr, B_WTIHR);
    k_tlstm<<<ceil_div(HID * G4, 256), 256>>>(W_hhr, B_WTHHR);
    k_bsum<<<ceil_div(G4, 256), 256>>>(b_ih,  b_hh,  B_BSUM);
    k_bsum<<<ceil_div(G4, 256), 256>>>(b_ihr, b_hhr, B_BSUMR);

    // conv: each conv is ONE GEMM (taps are contiguous rows of xpad -> K = k*IDIM,
    // lda = IDIM with overlapping A windows). bias + LeakyReLU fused in epilogue.
    for (int c = 0; c < 3; c++) {
        int k = ks[c], p = k / 2, chOff = 256 * c;
        gemm(B_XPAD, (size_t)(3 - p) * IDIM, IDIM,
             B_CWT, (size_t)planeBase[c] * IDIM * 256, 256,
             B_XFEAT, (size_t)chOff, HID,
             N, 256, k * IDIM,
             cb[c], -1, 0, /*leaky=*/1);
    }
    k_pool<<<ceil_div(N * HID, 256), 256>>>(N);

    // scan gates x-part: G = xpool @ Wih^T + (b_ih + b_hh)
    gemm(B_XPOOL, 0, HID, B_WTIH, 0, G4, B_G, 0, G4, N, G4, HID, 0, B_BSUM, 0);
    k_zero_hc<<<ceil_div(18 * HID, 256), 256>>>(N);
    scan_k<<<SCAN_NB, 256, 16 * HID * sizeof(float)>>>(W_hh, N, n_chunks);

    // forward final cell: gates = xfeat@Wih^T + bsum + h_prev@Whh^T
    gemm(B_XFEAT, 0, HID, B_WTIH, 0, G4, B_G, 0, G4, N, G4, HID, 0, B_BSUM, 0);
    gemm(B_HBUF, 0, HID, B_WTHH, 0, G4, B_G, 0, G4, N, G4, HID, 0, -1, 1);
    k_final<<<ceil_div(N * HID, 256), 256>>>(out, N, 0);

    // reverse final cell: gates = xfeat@Wihr^T + bsumr + h_next@Whhr^T
    gemm(B_XFEAT, 0, HID, B_WTIHR, 0, G4, B_G, 0, G4, N, G4, HID, 0, B_BSUMR, 0);
    gemm(B_HBUF, (size_t)18 * HID, HID, B_WTHHR, 0, G4, B_G, 0, G4, N, G4, HID, 0, -1, 1);
    k_final<<<ceil_div(N * HID, 256), 256>>>(out, N, 1);
}

// round 8
// speedup vs baseline: 1.1182x; 1.0571x over previous
#include <cuda_runtime.h>
#include <math.h>

#define MAXN 25600
#define IDIM 1068
#define HID  768
#define G4   3072
#define NDOCS 128

// ---------------- scratch (static device memory; no allocs allowed) ----------
__device__ float d_xpad[(MAXN + 6) * IDIM];
__device__ float d_cwt[15 * IDIM * 256];
__device__ float d_wtih[HID * G4];
__device__ float d_wthh[HID * G4];
__device__ float d_wtihr[HID * G4];
__device__ float d_wthhr[HID * G4];
__device__ float d_bsum[G4], d_bsumr[G4];
__device__ float d_xfeat[MAXN * HID];
__device__ float d_xpool[MAXN * HID];
__device__ float d_G[(size_t)MAXN * G4];
__device__ float d_hbuf[(MAXN + 18) * HID];
__device__ float d_cbuf[(MAXN + 18) * HID];
__device__ int   d_pos[MAXN];
__device__ int   d_off[NDOCS + 1];
__device__ unsigned d_bar;

#define B_XPAD  0
#define B_CWT   1
#define B_WTIH  2
#define B_WTHH  3
#define B_WTIHR 4
#define B_WTHHR 5
#define B_XFEAT 6
#define B_XPOOL 7
#define B_G     8
#define B_HBUF  9
#define B_BSUM  10
#define B_BSUMR 11

__device__ __forceinline__ float* buf_of(int id)
{
    switch (id) {
        case B_XPAD:  return d_xpad;
        case B_CWT:   return d_cwt;
        case B_WTIH:  return d_wtih;
        case B_WTHH:  return d_wthh;
        case B_WTIHR: return d_wtihr;
        case B_WTHHR: return d_wthhr;
        case B_XFEAT: return d_xfeat;
        case B_XPOOL: return d_xpool;
        case B_G:     return d_G;
        case B_HBUF:  return d_hbuf;
        case B_BSUM:  return d_bsum;
        case B_BSUMR: return d_bsumr;
        default:      return 0;
    }
}

__device__ __forceinline__ float sigm(float x) { return 1.f / (1.f + expf(-x)); }

// packed fp32x2 helpers
__device__ __forceinline__ unsigned long long bcast2(float x)
{
    unsigned long long r;
    asm("mov.b64 %0, {%1, %1};" : "=l"(r) : "r"(__float_as_uint(x)));
    return r;
}
__device__ __forceinline__ void ffma2(unsigned long long& d,
                                      unsigned long long a, unsigned long long b)
{
    asm("fma.rn.f32x2 %0, %1, %2, %0;" : "+l"(d) : "l"(a), "l"(b));
}
union F4U2 { float4 f; unsigned long long u[2]; };

// cp.async helpers
__device__ __forceinline__ unsigned smem_u32(const void* p)
{
    return (unsigned)__cvta_generic_to_shared(p);
}
__device__ __forceinline__ void cp16(unsigned s, const void* g, int src_bytes)
{
    asm volatile("cp.async.cg.shared.global [%0], [%1], 16, %2;"
                 :: "r"(s), "l"(g), "r"(src_bytes) : "memory");
}
__device__ __forceinline__ void cp_commit()
{
    asm volatile("cp.async.commit_group;" ::: "memory");
}
__device__ __forceinline__ void cp_wait1()
{
    asm volatile("cp.async.wait_group 1;" ::: "memory");
}

// ---------------- small setup kernels ---------------------------------------
__global__ void k_init(const int* __restrict__ lens)
{
    if (blockIdx.x == 0 && threadIdx.x == 0) {
        int s = 0; d_off[0] = 0;
        for (int i = 0; i < NDOCS; i++) { s += lens[i]; d_off[i + 1] = s; }
        d_bar = 0u;
    }
}

__global__ void k_pos(int N)
{
    int n = blockIdx.x * blockDim.x + threadIdx.x;
    if (n >= N) return;
    int lo = 0, hi = NDOCS;
    while (hi - lo > 1) { int mid = (lo + hi) >> 1; if (d_off[mid] <= n) lo = mid; else hi = mid; }
    d_pos[n] = n - d_off[lo];
}

__global__ void k_xpad(const float* __restrict__ x, int N)
{
    int idx = blockIdx.x * blockDim.x + threadIdx.x;
    int total = (N + 6) * IDIM;
    if (idx >= total) return;
    int r = idx / IDIM, dd = idx % IDIM;
    if (r < 3 || r >= N + 3) { d_xpad[idx] = 0.f; return; }
    int n = r - 3;
    int p = d_pos[n];
    int i = dd >> 1;
    float denom = powf(10000.f, (2.f * (float)i) / 1068.f);
    float ang = (float)p / denom;
    float pe = (dd & 1) ? cosf(ang) : sinf(ang);
    d_xpad[idx] = x[(size_t)n * IDIM + dd] + pe;
}

__global__ void k_tconv(const float* __restrict__ w, int k, size_t dstOff)
{
    int idx = blockIdx.x * blockDim.x + threadIdx.x;
    int total = k * IDIM * 256;
    if (idx >= total) return;
    int j = idx / (IDIM * 256);
    int r = idx % (IDIM * 256);
    int d = r / 256, c = r % 256;
    d_cwt[dstOff + idx] = w[(size_t)c * IDIM * k + (size_t)d * k + j];
}

__global__ void k_tlstm(const float* __restrict__ w, int dstId)
{
    int idx = blockIdx.x * blockDim.x + threadIdx.x;
    if (idx >= HID * G4) return;
    int f = idx / G4, g = idx % G4;
    buf_of(dstId)[idx] = w[(size_t)g * HID + f];
}

__global__ void k_bsum(const float* __restrict__ a, const float* __restrict__ b, int dstId)
{
    int i = blockIdx.x * blockDim.x + threadIdx.x;
    if (i < G4) buf_of(dstId)[i] = a[i] + b[i];
}

__global__ void k_pool(int N)
{
    int idx = blockIdx.x * blockDim.x + threadIdx.x;
    if (idx >= N * HID) return;
    int n = idx / HID, f = idx % HID;
    int p = (f < 256) ? 1 : ((f < 512) ? 2 : 3);
    int lo = n - p; if (lo < 0) lo = 0;
    int hi = n + p; if (hi > N - 1) hi = N - 1;
    float v = -INFINITY;
    for (int m = lo; m <= hi; m++) {
        float u = d_xfeat[(size_t)m * HID + f];
        v = (u > v) ? u : v;
    }
    d_xpool[idx] = v;
}

__global__ void k_zero_hc(int N)
{
    int idx = blockIdx.x * blockDim.x + threadIdx.x;
    if (idx >= 18 * HID) return;
    int i = idx / HID, ch = idx % HID;
    int row = (i < 9) ? i : (N + i);
    d_hbuf[(size_t)row * HID + ch] = 0.f;
    d_cbuf[(size_t)row * HID + ch] = 0.f;
}

// ---------------- SGEMM (f32x2, cp.async double-buffered, BK=16) -------------
// C[M,N] (=|+=) A[M,K] @ B[K,N]; optional bias + LeakyReLU in epilogue.
#define BKK 16

__global__ void __launch_bounds__(256, 2) sgemm_k(
    int aid, size_t aoff, int lda,
    int bid, size_t boff, int ldb,
    int cid, size_t coff, int ldc,
    int M, int N, int K,
    const float* __restrict__ bias_ext, int bias_id, int accflag, int leakyflag)
{
    const float* A = buf_of(aid) + aoff;
    const float* Bp = buf_of(bid) + boff;
    float*       C = buf_of(cid) + coff;
    const float* bias = (bias_id >= 0) ? buf_of(bias_id) : bias_ext;

    __shared__ __align__(16) float As[2][BKK][132];
    __shared__ __align__(16) float Bs[2][BKK][128];

    const int bm = blockIdx.y * 128, bn = blockIdx.x * 128;
    const int tid = threadIdx.x;
    const int tr = tid >> 4, tc = tid & 15;

    // B cp.async mapping: 512 16B-vectors per slice, 2 per thread
    //   v = tid + 256*i : kk = v>>5, n4 = (v&31)*4
    // A ldg mapping: 512 float4 per slice, 2 per thread
    //   v = tid + 256*i : m = v>>2, k4 = v&3
    const int S = (K + BKK - 1) / BKK;

    unsigned long long acc2[8][4];
#pragma unroll
    for (int i = 0; i < 8; i++)
#pragma unroll
        for (int j = 0; j < 4; j++) acc2[i][j] = 0ull;

    float4 regA[2];

    // ---- prologue: issue B slice0, load A slice0 into regs
    {
#pragma unroll
        for (int i = 0; i < 2; i++) {
            int v = tid + 256 * i;
            int kk = v >> 5, n4 = (v & 31) * 4;
            int gk = kk;                       // k0 = 0
            int ok = (gk < K);
            const float* g = Bp + (ok ? ((size_t)gk * ldb + bn + n4) : 0);
            cp16(smem_u32(&Bs[0][kk][n4]), g, ok ? 16 : 0);
        }
        cp_commit();
#pragma unroll
        for (int i = 0; i < 2; i++) {
            int v = tid + 256 * i;
            int m = v >> 2, k4 = v & 3;
            int gk = k4 * 4;
            if (gk < K)
                regA[i] = *(const float4*)(A + (size_t)(bm + m) * lda + gk);
            else
                regA[i] = make_float4(0.f, 0.f, 0.f, 0.f);
        }
    }

    for (int s = 0; s < S; ++s) {
        const int buf = s & 1;
        float4 regA2[2];
        // issue next slice's B cp.async + A LDG
        if (s + 1 < S) {
            int k0n = (s + 1) * BKK;
#pragma unroll
            for (int i = 0; i < 2; i++) {
                int v = tid + 256 * i;
                int kk = v >> 5, n4 = (v & 31) * 4;
                int gk = k0n + kk;
                int ok = (gk < K);
                const float* g = Bp + (ok ? ((size_t)gk * ldb + bn + n4) : 0);
                cp16(smem_u32(&Bs[buf ^ 1][kk][n4]), g, ok ? 16 : 0);
            }
#pragma unroll
            for (int i = 0; i < 2; i++) {
                int v = tid + 256 * i;
                int m = v >> 2, k4 = v & 3;
                int gk = k0n + k4 * 4;
                if (gk < K)
                    regA2[i] = *(const float4*)(A + (size_t)(bm + m) * lda + gk);
                else
                    regA2[i] = make_float4(0.f, 0.f, 0.f, 0.f);
            }
        }
        cp_commit();
        cp_wait1();                      // slice s's B group complete

        // store current A slice to smem (transposed [kk][m])
#pragma unroll
        for (int i = 0; i < 2; i++) {
            int v = tid + 256 * i;
            int m = v >> 2, k4 = v & 3;
            As[buf][k4 * 4 + 0][m] = regA[i].x;
            As[buf][k4 * 4 + 1][m] = regA[i].y;
            As[buf][k4 * 4 + 2][m] = regA[i].z;
            As[buf][k4 * 4 + 3][m] = regA[i].w;
        }
        __syncthreads();                 // A sts + B cp.async visible

#pragma unroll
        for (int kk = 0; kk < BKK; kk++) {
            float4 a0 = *(const float4*)&As[buf][kk][tr * 8];
            float4 a1 = *(const float4*)&As[buf][kk][tr * 8 + 4];
            F4U2 b0, b1;
            b0.f = *(const float4*)&Bs[buf][kk][tc * 8];
            b1.f = *(const float4*)&Bs[buf][kk][tc * 8 + 4];
            unsigned long long bb[4] = {b0.u[0], b0.u[1], b1.u[0], b1.u[1]};
            float av[8] = {a0.x, a0.y, a0.z, a0.w, a1.x, a1.y, a1.z, a1.w};
#pragma unroll
            for (int i = 0; i < 8; i++) {
                unsigned long long aa = bcast2(av[i]);
#pragma unroll
                for (int j = 0; j < 4; j++) ffma2(acc2[i][j], aa, bb[j]);
            }
        }
        regA[0] = regA2[0];
        regA[1] = regA2[1];
        __syncthreads();                 // all done reading buf before it is refilled
    }

#pragma unroll
    for (int i = 0; i < 8; i++) {
        int m = bm + tr * 8 + i;
        if (m < M) {
            float* crow = C + (size_t)m * ldc;
#pragma unroll
            for (int j = 0; j < 4; j++) {
#pragma unroll
                for (int h = 0; h < 2; h++) {
                    int n = bn + tc * 8 + 2 * j + h;
                    if (n < N) {
                        float v = h ? __uint_as_float((unsigned)(acc2[i][j] >> 32))
                                    : __uint_as_float((unsigned)acc2[i][j]);
                        if (accflag) {
                            crow[n] += v;
                        } else {
                            v += (bias ? bias[n] : 0.f);
                            if (leakyflag) v = (v >= 0.f) ? v : 0.01f * v;
                            crow[n] = v;
                        }
                    }
                }
            }
        }
    }
}

// ---------------- persistent chunked-LSTM scan -------------------------------
#define SCAN_NB 128
#define COLS_PB 6

__global__ void __launch_bounds__(256) scan_k(const float* __restrict__ Whh,
                                              int N, int n_chunks)
{
    extern __shared__ float sh[];
    const int tid = threadIdx.x;
    const int lane = tid & 31, warp = tid >> 5;
    const int colBase = blockIdx.x * COLS_PB;
    unsigned target = 0;

    for (int t = 0; t < n_chunks; ++t) {
        if (t == 0) {
            for (int i = tid; i < 16 * HID; i += 256) sh[i] = 0.f;
        } else {
            const float* src = d_hbuf + (size_t)(9 + (t - 1) * 16) * HID;
            for (int i = tid; i < 16 * HID; i += 256) sh[i] = __ldcg(src + i);
        }
        __syncthreads();

        float acc[3][16];
#pragma unroll
        for (int p = 0; p < 3; p++)
#pragma unroll
            for (int r = 0; r < 16; r++) acc[p][r] = 0.f;

        const float* wrow[3];
#pragma unroll
        for (int p = 0; p < 3; p++) {
            int pp = warp * 3 + p;
            int gate = pp / COLS_PB, cl = pp % COLS_PB;
            wrow[p] = Whh + (size_t)(gate * HID + colBase + cl) * HID;
        }
#pragma unroll 4
        for (int it = 0; it < 24; ++it) {
            int f = lane + 32 * it;
            float hreg[16];
#pragma unroll
            for (int r = 0; r < 16; r++) hreg[r] = sh[r * HID + f];
#pragma unroll
            for (int p = 0; p < 3; p++) {
                float w = __ldg(wrow[p] + f);
#pragma unroll
                for (int r = 0; r < 16; r++) acc[p][r] += w * hreg[r];
            }
        }
        __syncthreads();

#pragma unroll
        for (int p = 0; p < 3; p++) {
            int pp = warp * 3 + p;
            int gate = pp / COLS_PB, cl = pp % COLS_PB;
#pragma unroll
            for (int r = 0; r < 16; r++) {
                float v = acc[p][r];
                v += __shfl_down_sync(0xffffffffu, v, 16);
                v += __shfl_down_sync(0xffffffffu, v, 8);
                v += __shfl_down_sync(0xffffffffu, v, 4);
                v += __shfl_down_sync(0xffffffffu, v, 2);
                v += __shfl_down_sync(0xffffffffu, v, 1);
                if (lane == 0) sh[(cl * 4 + gate) * 16 + r] = v;
            }
        }
        __syncthreads();

        if (tid < 16 * COLS_PB) {
            int r = tid & 15, cl = tid >> 4;
            int n = t * 16 + r;
            if (n < N) {
                int col = colBase + cl;
                const float* g = d_G + (size_t)n * G4;
                float gi = g[col]        + sh[(cl * 4 + 0) * 16 + r];
                float gf = g[col + 768]  + sh[(cl * 4 + 1) * 16 + r];
                float gg = g[col + 1536] + sh[(cl * 4 + 2) * 16 + r];
                float go = g[col + 2304] + sh[(cl * 4 + 3) * 16 + r];
                float cp = (t == 0) ? 0.f : d_cbuf[(size_t)(9 + n - 16) * HID + col];
                float c2 = sigm(gf) * cp + sigm(gi) * tanhf(gg);
                d_hbuf[(size_t)(9 + n) * HID + col] = sigm(go) * tanhf(c2);
                d_cbuf[(size_t)(9 + n) * HID + col] = c2;
            }
        }
        __threadfence();
        __syncthreads();
        target += gridDim.x;
        if (tid == 0) {
            atomicAdd(&d_bar, 1u);
            while (*((volatile unsigned*)&d_bar) < target) { __nanosleep(20); }
        }
        __syncthreads();
        __threadfence();
    }
}

// ---------------- final LSTM cell epilogue ------------------------------------
__global__ void k_final(float* __restrict__ out, int N, int rev)
{
    int idx = blockIdx.x * blockDim.x + threadIdx.x;
    if (idx >= N * HID) return;
    int n = idx / HID, ch = idx % HID;
    const float* g = d_G + (size_t)n * G4;
    float gi = sigm(g[ch]);
    float gf = sigm(g[ch + 768]);
    float gg = tanhf(g[ch + 1536]);
    float go = sigm(g[ch + 2304]);
    float cp = d_cbuf[(size_t)(n + (rev ? 18 : 0)) * HID + ch];
    float c2 = gf * cp + gi * gg;
    out[(size_t)n * 1536 + (rev ? 768 : 0) + ch] = go * tanhf(c2);
}

// ---------------- host side ---------------------------------------------------
static inline int ceil_div(int a, int b) { return (a + b - 1) / b; }

static void gemm(int aid, size_t aoff, int lda, int bid, size_t boff, int ldb,
                 int cid, size_t coff, int ldc, int M, int N, int K,
                 const float* bias_ext, int bias_id, int acc, int leaky = 0)
{
    dim3 g(ceil_div(N, 128), ceil_div(M, 128));
    sgemm_k<<<g, 256>>>(aid, aoff, lda, bid, boff, ldb, cid, coff, ldc,
                        M, N, K, bias_ext, bias_id, acc, leaky);
}

extern "C" void kernel_launch(void* const* d_in, const int* in_sizes, int n_in,
                              void* d_out, int out_size)
{
    const float* x      = (const float*)d_in[0];
    const int*   lens   = (const int*)d_in[1];
    const float* cw[3]  = {(const float*)d_in[2], (const float*)d_in[4], (const float*)d_in[6]};
    const float* cb[3]  = {(const float*)d_in[3], (const float*)d_in[5], (const float*)d_in[7]};
    const float* W_ih   = (const float*)d_in[8];
    const float* W_hh   = (const float*)d_in[9];
    const float* b_ih   = (const float*)d_in[10];
    const float* b_hh   = (const float*)d_in[11];
    const float* W_ihr  = (const float*)d_in[12];
    const float* W_hhr  = (const float*)d_in[13];
    const float* b_ihr  = (const float*)d_in[14];
    const float* b_hhr  = (const float*)d_in[15];
    float* out = (float*)d_out;

    const int N = out_size / 1536;
    const int n_chunks = (N + 15) / 16;

    k_init<<<1, 32>>>(lens);
    k_pos<<<ceil_div(N, 256), 256>>>(N);
    k_xpad<<<ceil_div((N + 6) * IDIM, 256), 256>>>(x, N);

    const int ks[3] = {3, 5, 7};
    const int planeBase[3] = {0, 3, 8};
    for (int c = 0; c < 3; c++)
        k_tconv<<<ceil_div(ks[c] * IDIM * 256, 256), 256>>>(cw[c], ks[c],
                                                            (size_t)planeBase[c] * IDIM * 256);
    k_tlstm<<<ceil_div(HID * G4, 256), 256>>>(W_ih,  B_WTIH);
    k_tlstm<<<ceil_div(HID * G4, 256), 256>>>(W_hh,  B_WTHH);
    k_tlstm<<<ceil_div(HID * G4, 256), 256>>>(W_ihr, B_WTIHR);
    k_tlstm<<<ceil_div(HID * G4, 256), 256>>>(W_hhr, B_WTHHR);
    k_bsum<<<ceil_div(G4, 256), 256>>>(b_ih,  b_hh,  B_BSUM);
    k_bsum<<<ceil_div(G4, 256), 256>>>(b_ihr, b_hhr, B_BSUMR);

    // conv: one GEMM per kernel size (taps contiguous -> K = k*IDIM, lda = IDIM)
    for (int c = 0; c < 3; c++) {
        int k = ks[c], p = k / 2, chOff = 256 * c;
        gemm(B_XPAD, (size_t)(3 - p) * IDIM, IDIM,
             B_CWT, (size_t)planeBase[c] * IDIM * 256, 256,
             B_XFEAT, (size_t)chOff, HID,
             N, 256, k * IDIM,
             cb[c], -1, 0, /*leaky=*/1);
    }
    k_pool<<<ceil_div(N * HID, 256), 256>>>(N);

    // scan gates x-part: G = xpool @ Wih^T + (b_ih + b_hh)
    gemm(B_XPOOL, 0, HID, B_WTIH, 0, G4, B_G, 0, G4, N, G4, HID, 0, B_BSUM, 0);
    k_zero_hc<<<ceil_div(18 * HID, 256), 256>>>(N);
    scan_k<<<SCAN_NB, 256, 16 * HID * sizeof(float)>>>(W_hh, N, n_chunks);

    // forward final cell
    gemm(B_XFEAT, 0, HID, B_WTIH, 0, G4, B_G, 0, G4, N, G4, HID, 0, B_BSUM, 0);
    gemm(B_HBUF, 0, HID, B_WTHH, 0, G4, B_G, 0, G4, N, G4, HID, 0, -1, 1);
    k_final<<<ceil_div(N * HID, 256), 256>>>(out, N, 0);

    // reverse final cell
    gemm(B_XFEAT, 0, HID, B_WTIHR, 0, G4, B_G, 0, G4, N, G4, HID, 0, B_BSUMR, 0);
    gemm(B_HBUF, (size_t)18 * HID, HID, B_WTHHR, 0, G4, B_G, 0, G4, N, G4, HID, 0, -1, 1);
    k_final<<<ceil_div(N * HID, 256), 256>>>(out, N, 1);
}

// round 9
// speedup vs baseline: 1.4088x; 1.2599x over previous
#include <cuda_runtime.h>
#include <cuda_bf16.h>
#include <math.h>

#define MAXN 25600
#define IDIM 1068
#define HID  768
#define G4   3072
#define NDOCS 128
#define CBT_STRIDE 7480

// ---------------- fp32 scratch ------------------------------------------------
__device__ float d_xpad[(MAXN + 6) * IDIM];
__device__ float d_bsum[G4], d_bsumr[G4];
__device__ float d_xfeat[MAXN * HID];
__device__ float d_xpool[MAXN * HID];
__device__ float d_G[(size_t)MAXN * G4];
__device__ float d_hbuf[(MAXN + 18) * HID];
__device__ float d_cbuf[(MAXN + 18) * HID];
__device__ int   d_pos[MAXN];
__device__ int   d_off[NDOCS + 1];
__device__ unsigned d_bar;

// ---------------- bf16 (hi/lo split) scratch ----------------------------------
__device__ unsigned short h_xpad[2][(MAXN + 6) * IDIM + 8];
__device__ unsigned short h_cbt[2][3 * 256 * CBT_STRIDE];
__device__ unsigned short h_wih[2][G4 * HID];
__device__ unsigned short h_whh[2][G4 * HID];
__device__ unsigned short h_wihr[2][G4 * HID];
__device__ unsigned short h_whhr[2][G4 * HID];
__device__ unsigned short h_xfeat[2][MAXN * HID];
__device__ unsigned short h_xpool[2][MAXN * HID];
__device__ unsigned short h_hbuf[2][(MAXN + 18) * HID];

// fp32 buffer ids
#define B_XPAD  0
#define B_XFEAT 1
#define B_XPOOL 2
#define B_G     3
#define B_HBUF  4
#define B_BSUM  5
#define B_BSUMR 6

__device__ __forceinline__ float* buf_of(int id)
{
    switch (id) {
        case B_XPAD:  return d_xpad;
        case B_XFEAT: return d_xfeat;
        case B_XPOOL: return d_xpool;
        case B_G:     return d_G;
        case B_HBUF:  return d_hbuf;
        case B_BSUM:  return d_bsum;
        case B_BSUMR: return d_bsumr;
        default:      return 0;
    }
}

// bf16 buffer ids
#define H_XPAD  0
#define H_CBT   1
#define H_WIH   2
#define H_WHH   3
#define H_WIHR  4
#define H_WHHR  5
#define H_XFEAT 6
#define H_XPOOL 7
#define H_HBUF  8

__device__ __forceinline__ unsigned short* bf16_of(int id, int h)
{
    switch (id) {
        case H_XPAD:  return h_xpad[h];
        case H_CBT:   return h_cbt[h];
        case H_WIH:   return h_wih[h];
        case H_WHH:   return h_whh[h];
        case H_WIHR:  return h_wihr[h];
        case H_WHHR:  return h_whhr[h];
        case H_XFEAT: return h_xfeat[h];
        case H_XPOOL: return h_xpool[h];
        case H_HBUF:  return h_hbuf[h];
        default:      return 0;
    }
}

__device__ __forceinline__ float sigm(float x) { return 1.f / (1.f + expf(-x)); }

// cp.async helpers
__device__ __forceinline__ unsigned smem_u32(const void* p)
{
    return (unsigned)__cvta_generic_to_shared(p);
}
__device__ __forceinline__ void cp16(unsigned s, const void* g, int src_bytes)
{
    asm volatile("cp.async.cg.shared.global [%0], [%1], 16, %2;"
                 :: "r"(s), "l"(g), "r"(src_bytes) : "memory");
}
__device__ __forceinline__ void cp8(unsigned s, const void* g, int src_bytes)
{
    asm volatile("cp.async.ca.shared.global [%0], [%1], 8, %2;"
                 :: "r"(s), "l"(g), "r"(src_bytes) : "memory");
}
__device__ __forceinline__ void cp_commit()
{
    asm volatile("cp.async.commit_group;" ::: "memory");
}
__device__ __forceinline__ void cp_wait1()
{
    asm volatile("cp.async.wait_group 1;" ::: "memory");
}

// bf16 mma
__device__ __forceinline__ void mma16816(float* c, const unsigned* a, const unsigned* b)
{
    asm volatile(
        "mma.sync.aligned.m16n8k16.row.col.f32.bf16.bf16.f32 "
        "{%0,%1,%2,%3}, {%4,%5,%6,%7}, {%8,%9}, {%0,%1,%2,%3};"
        : "+f"(c[0]), "+f"(c[1]), "+f"(c[2]), "+f"(c[3])
        : "r"(a[0]), "r"(a[1]), "r"(a[2]), "r"(a[3]), "r"(b[0]), "r"(b[1]));
}

// ---------------- setup kernels ------------------------------------------------
__global__ void k_init(const int* __restrict__ lens)
{
    if (blockIdx.x == 0 && threadIdx.x == 0) {
        int s = 0; d_off[0] = 0;
        for (int i = 0; i < NDOCS; i++) { s += lens[i]; d_off[i + 1] = s; }
        d_bar = 0u;
    }
}

__global__ void k_pos(int N)
{
    int n = blockIdx.x * blockDim.x + threadIdx.x;
    if (n >= N) return;
    int lo = 0, hi = NDOCS;
    while (hi - lo > 1) { int mid = (lo + hi) >> 1; if (d_off[mid] <= n) lo = mid; else hi = mid; }
    d_pos[n] = n - d_off[lo];
}

__global__ void k_xpad(const float* __restrict__ x, int N)
{
    int idx = blockIdx.x * blockDim.x + threadIdx.x;
    int total = (N + 6) * IDIM;
    if (idx >= total) return;
    int r = idx / IDIM, dd = idx % IDIM;
    if (r < 3 || r >= N + 3) { d_xpad[idx] = 0.f; return; }
    int n = r - 3;
    int p = d_pos[n];
    int i = dd >> 1;
    float denom = powf(10000.f, (2.f * (float)i) / 1068.f);
    float ang = (float)p / denom;
    float pe = (dd & 1) ? cosf(ang) : sinf(ang);
    d_xpad[idx] = x[(size_t)n * IDIM + dd] + pe;
}

// split fp32 buffer -> bf16 hi/lo pair
__global__ void k_split(int srcId, int dstId, int n)
{
    int i = blockIdx.x * blockDim.x + threadIdx.x;
    if (i >= n) return;
    float v = buf_of(srcId)[i];
    __nv_bfloat16 hb = __float2bfloat16(v);
    float r = v - __bfloat162float(hb);
    bf16_of(dstId, 0)[i] = __bfloat16_as_ushort(hb);
    bf16_of(dstId, 1)[i] = __bfloat16_as_ushort(__float2bfloat16(r));
}

// split external fp32 array -> bf16 pair
__global__ void k_splitW(const float* __restrict__ src, int dstId, int n)
{
    int i = blockIdx.x * blockDim.x + threadIdx.x;
    if (i >= n) return;
    float v = src[i];
    __nv_bfloat16 hb = __float2bfloat16(v);
    float r = v - __bfloat162float(hb);
    bf16_of(dstId, 0)[i] = __bfloat16_as_ushort(hb);
    bf16_of(dstId, 1)[i] = __bfloat16_as_ushort(__float2bfloat16(r));
}

// conv weights: w[oc][in][j] -> Bt[oc][j*1068+d] bf16 hi/lo, rows padded to Ks (zeros)
__global__ void k_tconv2(const float* __restrict__ w, int k, int Ks, int c)
{
    int idx = blockIdx.x * blockDim.x + threadIdx.x;
    int total = 256 * Ks;
    if (idx >= total) return;
    int oc = idx / Ks, col = idx % Ks;
    float v = 0.f;
    if (col < k * IDIM) {
        int j = col / IDIM, d = col % IDIM;
        v = w[(size_t)oc * IDIM * k + (size_t)d * k + j];
    }
    __nv_bfloat16 hb = __float2bfloat16(v);
    float r = v - __bfloat162float(hb);
    size_t o = (size_t)c * 256 * CBT_STRIDE + idx;
    h_cbt[0][o] = __bfloat16_as_ushort(hb);
    h_cbt[1][o] = __bfloat16_as_ushort(__float2bfloat16(r));
}

__global__ void k_bsum(const float* __restrict__ a, const float* __restrict__ b, int dstId)
{
    int i = blockIdx.x * blockDim.x + threadIdx.x;
    if (i < G4) buf_of(dstId)[i] = a[i] + b[i];
}

__global__ void k_pool(int N)
{
    int idx = blockIdx.x * blockDim.x + threadIdx.x;
    if (idx >= N * HID) return;
    int n = idx / HID, f = idx % HID;
    int p = (f < 256) ? 1 : ((f < 512) ? 2 : 3);
    int lo = n - p; if (lo < 0) lo = 0;
    int hi = n + p; if (hi > N - 1) hi = N - 1;
    float v = -INFINITY;
    for (int m = lo; m <= hi; m++) {
        float u = d_xfeat[(size_t)m * HID + f];
        v = (u > v) ? u : v;
    }
    d_xpool[idx] = v;
}

__global__ void k_zero_hc(int N)
{
    int idx = blockIdx.x * blockDim.x + threadIdx.x;
    if (idx >= 18 * HID) return;
    int i = idx / HID, ch = idx % HID;
    int row = (i < 9) ? i : (N + i);
    d_hbuf[(size_t)row * HID + ch] = 0.f;
    d_cbuf[(size_t)row * HID + ch] = 0.f;
}

// ---------------- bf16 tensor-core GEMM ---------------------------------------
// C[M,Nn] (=|+=) 3-pass split GEMM: Ah@Bh + Ah@Bl + Al@Bh
// A: [M,K] bf16 row-major (lda elems). B: [Nn,K] bf16 row-major (ldbt elems) == B^T.
// Block 128x128, BK=32, 8 warps (2x4), warp tile 64x32.
__global__ void __launch_bounds__(256, 2) gemm16_k(
    int aid, size_t aoff, int lda,
    int bid, size_t boff, int ldbt,
    int cid, size_t coff, int ldc,
    int M, int Nn, int K, int Ks,
    const float* __restrict__ bias_ext, int bias_id, int accflag, int leakyflag)
{
    const unsigned short* Ah = bf16_of(aid, 0) + aoff;
    const unsigned short* Al = bf16_of(aid, 1) + aoff;
    const unsigned short* Bh = bf16_of(bid, 0) + boff;
    const unsigned short* Bl = bf16_of(bid, 1) + boff;
    float* C = buf_of(cid) + coff;
    const float* bias = (bias_id >= 0) ? buf_of(bias_id) : bias_ext;

    // padded smem: 128 rows x 40 bf16 (20 words) per buffer
    __shared__ unsigned As[2][2560];
    __shared__ unsigned Bs2[2][2560];

    const int tid = threadIdx.x;
    const int warp = tid >> 5, lane = tid & 31;
    const int g = lane >> 2, t = lane & 3;
    const int wm0 = (warp >> 2) * 64, wn0 = (warp & 3) * 32;
    const int bm = blockIdx.y * 128, bn = blockIdx.x * 128;

    float acc[4][4][4];
#pragma unroll
    for (int i = 0; i < 4; i++)
#pragma unroll
        for (int j = 0; j < 4; j++)
#pragma unroll
            for (int e = 0; e < 4; e++) acc[i][j][e] = 0.f;

    const int S = (Ks + 31) / 32;
    const unsigned aS0 = smem_u32(&As[0][0]);
    const unsigned aS1 = smem_u32(&As[1][0]);
    const unsigned bS0 = smem_u32(&Bs2[0][0]);
    const unsigned bS1 = smem_u32(&Bs2[1][0]);

    for (int pass = 0; pass < 3; ++pass) {
        const unsigned short* Ap = (pass == 2) ? Al : Ah;
        const unsigned short* Bp = (pass == 1) ? Bl : Bh;

        // prologue: slice 0 -> buf 0
        {
#pragma unroll
            for (int i = 0; i < 4; i++) {
                int v = tid + 256 * i;
                int row = v >> 3, ch = v & 7;
                int gk = ch * 4;
                int rem = (bm + row < M) ? (K - gk) : 0;
                int bytes = rem >= 4 ? 8 : 0;
                const void* src = bytes ? (const void*)(Ap + (size_t)(bm + row) * lda + gk)
                                        : (const void*)Ap;
                cp8(aS0 + row * 80 + ch * 8, src, bytes);
            }
#pragma unroll
            for (int i = 0; i < 2; i++) {
                int v = tid + 256 * i;
                int row = v >> 2, ch = v & 3;
                int gk = ch * 8;
                int rem = Ks - gk;
                int bytes = rem >= 8 ? 16 : 0;
                const void* src = bytes ? (const void*)(Bp + (size_t)(bn + row) * ldbt + gk)
                                        : (const void*)Bp;
                cp16(bS0 + row * 80 + ch * 16, src, bytes);
            }
            cp_commit();
        }

        for (int s = 0; s < S; ++s) {
            const int buf = s & 1;
            if (s + 1 < S) {
                int k0 = (s + 1) * 32;
                unsigned aD = buf ? aS0 : aS1;
                unsigned bD = buf ? bS0 : bS1;
#pragma unroll
                for (int i = 0; i < 4; i++) {
                    int v = tid + 256 * i;
                    int row = v >> 3, ch = v & 7;
                    int gk = k0 + ch * 4;
                    int rem = (bm + row < M) ? (K - gk) : 0;
                    int bytes = rem >= 4 ? 8 : 0;
                    const void* src = bytes ? (const void*)(Ap + (size_t)(bm + row) * lda + gk)
                                            : (const void*)Ap;
                    cp8(aD + row * 80 + ch * 8, src, bytes);
                }
#pragma unroll
                for (int i = 0; i < 2; i++) {
                    int v = tid + 256 * i;
                    int row = v >> 2, ch = v & 3;
                    int gk = k0 + ch * 8;
                    int rem = Ks - gk;
                    int bytes = rem >= 8 ? 16 : 0;
                    const void* src = bytes ? (const void*)(Bp + (size_t)(bn + row) * ldbt + gk)
                                            : (const void*)Bp;
                    cp16(bD + row * 80 + ch * 16, src, bytes);
                }
            }
            cp_commit();
            cp_wait1();
            __syncthreads();

#pragma unroll
            for (int kh = 0; kh < 2; kh++) {
                unsigned af[4][4], bfr[4][2];
#pragma unroll
                for (int mt = 0; mt < 4; mt++) {
                    int r = wm0 + mt * 16 + g;
                    int w0 = r * 20 + kh * 8 + t;
                    af[mt][0] = As[buf][w0];
                    af[mt][1] = As[buf][w0 + 160];
                    af[mt][2] = As[buf][w0 + 4];
                    af[mt][3] = As[buf][w0 + 164];
                }
#pragma unroll
                for (int nt = 0; nt < 4; nt++) {
                    int r = wn0 + nt * 8 + g;
                    int w0 = r * 20 + kh * 8 + t;
                    bfr[nt][0] = Bs2[buf][w0];
                    bfr[nt][1] = Bs2[buf][w0 + 4];
                }
#pragma unroll
                for (int mt = 0; mt < 4; mt++)
#pragma unroll
                    for (int nt = 0; nt < 4; nt++)
                        mma16816(acc[mt][nt], af[mt], bfr[nt]);
            }
            __syncthreads();
        }
    }

    // epilogue
#pragma unroll
    for (int mt = 0; mt < 4; mt++) {
        int r0 = bm + wm0 + mt * 16 + g;
#pragma unroll
        for (int nt = 0; nt < 4; nt++) {
            int c0 = bn + wn0 + nt * 8 + 2 * t;
#pragma unroll
            for (int e = 0; e < 4; e++) {
                int rr = r0 + (e >> 1) * 8;
                int cc = c0 + (e & 1);
                if (rr < M) {
                    float v = acc[mt][nt][e];
                    float* p = C + (size_t)rr * ldc + cc;
                    if (accflag) {
                        *p += v;
                    } else {
                        v += bias ? bias[cc] : 0.f;
                        if (leakyflag) v = (v >= 0.f) ? v : 0.01f * v;
                        *p = v;
                    }
                }
            }
        }
    }
}

// ---------------- persistent chunked-LSTM scan -------------------------------
#define SCAN_NB 128
#define COLS_PB 6

__global__ void __launch_bounds__(256) scan_k(const float* __restrict__ Whh,
                                              int N, int n_chunks)
{
    extern __shared__ float sh[];
    const int tid = threadIdx.x;
    const int lane = tid & 31, warp = tid >> 5;
    const int colBase = blockIdx.x * COLS_PB;
    unsigned target = 0;

    for (int t = 0; t < n_chunks; ++t) {
        if (t == 0) {
            for (int i = tid; i < 16 * HID; i += 256) sh[i] = 0.f;
        } else {
            const float* src = d_hbuf + (size_t)(9 + (t - 1) * 16) * HID;
            for (int i = tid; i < 16 * HID; i += 256) sh[i] = __ldcg(src + i);
        }
        __syncthreads();

        float acc[3][16];
#pragma unroll
        for (int p = 0; p < 3; p++)
#pragma unroll
            for (int r = 0; r < 16; r++) acc[p][r] = 0.f;

        const float* wrow[3];
#pragma unroll
        for (int p = 0; p < 3; p++) {
            int pp = warp * 3 + p;
            int gate = pp / COLS_PB, cl = pp % COLS_PB;
            wrow[p] = Whh + (size_t)(gate * HID + colBase + cl) * HID;
        }
#pragma unroll 4
        for (int it = 0; it < 24; ++it) {
            int f = lane + 32 * it;
            float hreg[16];
#pragma unroll
            for (int r = 0; r < 16; r++) hreg[r] = sh[r * HID + f];
#pragma unroll
            for (int p = 0; p < 3; p++) {
                float w = __ldg(wrow[p] + f);
#pragma unroll
                for (int r = 0; r < 16; r++) acc[p][r] += w * hreg[r];
            }
        }
        __syncthreads();

#pragma unroll
        for (int p = 0; p < 3; p++) {
            int pp = warp * 3 + p;
            int gate = pp / COLS_PB, cl = pp % COLS_PB;
#pragma unroll
            for (int r = 0; r < 16; r++) {
                float v = acc[p][r];
                v += __shfl_down_sync(0xffffffffu, v, 16);
                v += __shfl_down_sync(0xffffffffu, v, 8);
                v += __shfl_down_sync(0xffffffffu, v, 4);
                v += __shfl_down_sync(0xffffffffu, v, 2);
                v += __shfl_down_sync(0xffffffffu, v, 1);
                if (lane == 0) sh[(cl * 4 + gate) * 16 + r] = v;
            }
        }
        __syncthreads();

        if (tid < 16 * COLS_PB) {
            int r = tid & 15, cl = tid >> 4;
            int n = t * 16 + r;
            if (n < N) {
                int col = colBase + cl;
                const float* gq = d_G + (size_t)n * G4;
                float gi = gq[col]        + sh[(cl * 4 + 0) * 16 + r];
                float gf = gq[col + 768]  + sh[(cl * 4 + 1) * 16 + r];
                float gg = gq[col + 1536] + sh[(cl * 4 + 2) * 16 + r];
                float go = gq[col + 2304] + sh[(cl * 4 + 3) * 16 + r];
                float cp = (t == 0) ? 0.f : d_cbuf[(size_t)(9 + n - 16) * HID + col];
                float c2 = sigm(gf) * cp + sigm(gi) * tanhf(gg);
                d_hbuf[(size_t)(9 + n) * HID + col] = sigm(go) * tanhf(c2);
                d_cbuf[(size_t)(9 + n) * HID + col] = c2;
            }
        }
        __threadfence();
        __syncthreads();
        target += gridDim.x;
        if (tid == 0) {
            atomicAdd(&d_bar, 1u);
            while (*((volatile unsigned*)&d_bar) < target) { __nanosleep(20); }
        }
        __syncthreads();
        __threadfence();
    }
}

// ---------------- final LSTM cell epilogue ------------------------------------
__global__ void k_final(float* __restrict__ out, int N, int rev)
{
    int idx = blockIdx.x * blockDim.x + threadIdx.x;
    if (idx >= N * HID) return;
    int n = idx / HID, ch = idx % HID;
    const float* g = d_G + (size_t)n * G4;
    float gi = sigm(g[ch]);
    float gf = sigm(g[ch + 768]);
    float gg = tanhf(g[ch + 1536]);
    float go = sigm(g[ch + 2304]);
    float cp = d_cbuf[(size_t)(n + (rev ? 18 : 0)) * HID + ch];
    float c2 = gf * cp + gi * gg;
    out[(size_t)n * 1536 + (rev ? 768 : 0) + ch] = go * tanhf(c2);
}

// ---------------- host side ---------------------------------------------------
static inline int ceil_div(int a, int b) { return (a + b - 1) / b; }

static void gemm16(int aid, size_t aoff, int lda, int bid, size_t boff, int ldbt,
                   int cid, size_t coff, int ldc, int M, int Nn, int K, int Ks,
                   const float* bias_ext, int bias_id, int acc, int leaky = 0)
{
    dim3 g(Nn / 128, ceil_div(M, 128));
    gemm16_k<<<g, 256>>>(aid, aoff, lda, bid, boff, ldbt, cid, coff, ldc,
                         M, Nn, K, Ks, bias_ext, bias_id, acc, leaky);
}

extern "C" void kernel_launch(void* const* d_in, const int* in_sizes, int n_in,
                              void* d_out, int out_size)
{
    const float* x      = (const float*)d_in[0];
    const int*   lens   = (const int*)d_in[1];
    const float* cw[3]  = {(const float*)d_in[2], (const float*)d_in[4], (const float*)d_in[6]};
    const float* cb[3]  = {(const float*)d_in[3], (const float*)d_in[5], (const float*)d_in[7]};
    const float* W_ih   = (const float*)d_in[8];
    const float* W_hh   = (const float*)d_in[9];
    const float* b_ih   = (const float*)d_in[10];
    const float* b_hh   = (const float*)d_in[11];
    const float* W_ihr  = (const float*)d_in[12];
    const float* W_hhr  = (const float*)d_in[13];
    const float* b_ihr  = (const float*)d_in[14];
    const float* b_hhr  = (const float*)d_in[15];
    float* out = (float*)d_out;

    const int N = out_size / 1536;
    const int n_chunks = (N + 15) / 16;

    k_init<<<1, 32>>>(lens);
    k_pos<<<ceil_div(N, 256), 256>>>(N);
    k_xpad<<<ceil_div((N + 6) * IDIM, 256), 256>>>(x, N);
    k_split<<<ceil_div((N + 6) * IDIM, 256), 256>>>(B_XPAD, H_XPAD, (N + 6) * IDIM);

    const int ks[3] = {3, 5, 7};
    int Ksv[3];
    for (int c = 0; c < 3; c++) {
        int K = ks[c] * IDIM;
        Ksv[c] = (K + 7) & ~7;
        k_tconv2<<<ceil_div(256 * Ksv[c], 256), 256>>>(cw[c], ks[c], Ksv[c], c);
    }
    k_splitW<<<ceil_div(G4 * HID, 256), 256>>>(W_ih,  H_WIH,  G4 * HID);
    k_splitW<<<ceil_div(G4 * HID, 256), 256>>>(W_hh,  H_WHH,  G4 * HID);
    k_splitW<<<ceil_div(G4 * HID, 256), 256>>>(W_ihr, H_WIHR, G4 * HID);
    k_splitW<<<ceil_div(G4 * HID, 256), 256>>>(W_hhr, H_WHHR, G4 * HID);
    k_bsum<<<ceil_div(G4, 256), 256>>>(b_ih,  b_hh,  B_BSUM);
    k_bsum<<<ceil_div(G4, 256), 256>>>(b_ihr, b_hhr, B_BSUMR);

    // conv: one tensor GEMM per kernel size; bias + LeakyReLU fused
    for (int c = 0; c < 3; c++) {
        int k = ks[c], p = k / 2, chOff = 256 * c;
        gemm16(H_XPAD, (size_t)(3 - p) * IDIM, IDIM,
               H_CBT, (size_t)c * 256 * CBT_STRIDE, Ksv[c],
               B_XFEAT, (size_t)chOff, HID,
               N, 256, k * IDIM, Ksv[c],
               cb[c], -1, 0, /*leaky=*/1);
    }
    k_pool<<<ceil_div(N * HID, 256), 256>>>(N);
    k_split<<<ceil_div(N * HID, 256), 256>>>(B_XFEAT, H_XFEAT, N * HID);
    k_split<<<ceil_div(N * HID, 256), 256>>>(B_XPOOL, H_XPOOL, N * HID);

    // scan gates x-part: G = xpool @ W_ih^T + (b_ih + b_hh)
    gemm16(H_XPOOL, 0, HID, H_WIH, 0, HID, B_G, 0, G4, N, G4, HID, HID, 0, B_BSUM, 0);
    k_zero_hc<<<ceil_div(18 * HID, 256), 256>>>(N);
    scan_k<<<SCAN_NB, 256, 16 * HID * sizeof(float)>>>(W_hh, N, n_chunks);
    k_split<<<ceil_div((N + 18) * HID, 256), 256>>>(B_HBUF, H_HBUF, (N + 18) * HID);

    // forward final cell
    gemm16(H_XFEAT, 0, HID, H_WIH, 0, HID, B_G, 0, G4, N, G4, HID, HID, 0, B_BSUM, 0);
    gemm16(H_HBUF, 0, HID, H_WHH, 0, HID, B_G, 0, G4, N, G4, HID, HID, 0, -1, 1);
    k_final<<<ceil_div(N * HID, 256), 256>>>(out, N, 0);

    // reverse final cell
    gemm16(H_XFEAT, 0, HID, H_WIHR, 0, HID, B_G, 0, G4, N, G4, HID, HID, 0, B_BSUMR, 0);
    gemm16(H_HBUF, (size_t)18 * HID, HID, H_WHHR, 0, HID, B_G, 0, G4, N, G4, HID, HID, 0, -1, 1);
    k_final<<<ceil_div(N * HID, 256), 256>>>(out, N, 1);
}